// round 1
// baseline (speedup 1.0000x reference)
#include <cuda_runtime.h>

#define NGROUPS 8
#define THREADS 256
#define ELEMS_PER_THREAD 16

// Global scratch (no allocations allowed) — zeroed by zero_kernel each launch.
__device__ float g_sums[NGROUPS];
__device__ float g_cnts[NGROUPS];

__global__ void zero_kernel() {
    int t = threadIdx.x;
    if (t < NGROUPS) { g_sums[t] = 0.0f; g_cnts[t] = 0.0f; }
}

__global__ __launch_bounds__(THREADS) void accum_kernel(
    const float* __restrict__ in, const int* __restrict__ tgt,
    const int* __restrict__ grp, int n)
{
    float s[NGROUPS], c[NGROUPS];
#pragma unroll
    for (int j = 0; j < NGROUPS; j++) { s[j] = 0.0f; c[j] = 0.0f; }

    int tid = blockIdx.x * blockDim.x + threadIdx.x;
    int total = gridDim.x * blockDim.x;

    // Lane-consecutive rows: lanes l, l+1 share a 128B line on the gather
    // (rows are 64B), halving L1tex wavefronts vs per-thread row blocks.
#pragma unroll 4
    for (int i = tid; i < n; i += total) {
        int t = __ldcs(tgt + i);
        int g = __ldcs(grp + i);
        float v = __ldcs(in + (size_t)i * 16 + t);
        float e = fabsf(1.0f - v);
#pragma unroll
        for (int j = 0; j < NGROUPS; j++) {
            bool m = (g == j);
            s[j] += m ? e : 0.0f;
            c[j] += m ? 1.0f : 0.0f;   // counts as float: exact (< 2^24)
        }
    }

    // Warp reduction
#pragma unroll
    for (int j = 0; j < NGROUPS; j++) {
#pragma unroll
        for (int o = 16; o > 0; o >>= 1) {
            s[j] += __shfl_down_sync(0xffffffffu, s[j], o);
            c[j] += __shfl_down_sync(0xffffffffu, c[j], o);
        }
    }

    __shared__ float wsum[THREADS / 32][NGROUPS];
    __shared__ float wcnt[THREADS / 32][NGROUPS];
    int lane = threadIdx.x & 31;
    int warp = threadIdx.x >> 5;
    if (lane == 0) {
#pragma unroll
        for (int j = 0; j < NGROUPS; j++) { wsum[warp][j] = s[j]; wcnt[warp][j] = c[j]; }
    }
    __syncthreads();

    if (threadIdx.x < NGROUPS) {
        float ts = 0.0f, tc = 0.0f;
#pragma unroll
        for (int w = 0; w < THREADS / 32; w++) {
            ts += wsum[w][threadIdx.x];
            tc += wcnt[w][threadIdx.x];
        }
        atomicAdd(&g_sums[threadIdx.x], ts);
        atomicAdd(&g_cnts[threadIdx.x], tc);
    }
}

__global__ void finalize_kernel(float* __restrict__ out) {
    int t = threadIdx.x;
    float m = 0.0f;
    if (t < NGROUPS) {
        float cnt = g_cnts[t];
        m = (cnt > 0.0f) ? (g_sums[t] / cnt) : 0.0f;
    }
#pragma unroll
    for (int o = 16; o > 0; o >>= 1)
        m += __shfl_down_sync(0xffffffffu, m, o);
    if (t == 0) out[0] = fabsf(0.5f - m * (1.0f / NGROUPS));
}

extern "C" void kernel_launch(void* const* d_in, const int* in_sizes, int n_in,
                              void* d_out, int out_size) {
    const float* in  = (const float*)d_in[0];
    const int*   tgt = (const int*)d_in[1];
    const int*   grp = (const int*)d_in[2];
    float*       out = (float*)d_out;
    int n = in_sizes[1];  // N rows

    zero_kernel<<<1, 32>>>();

    int per_block = THREADS * ELEMS_PER_THREAD;
    int blocks = (n + per_block - 1) / per_block;   // 1024 for N=4M
    if (blocks < 1) blocks = 1;
    accum_kernel<<<blocks, THREADS>>>(in, tgt, grp, n);

    finalize_kernel<<<1, 32>>>(out);
}